// round 1
// baseline (speedup 1.0000x reference)
#include <cuda_runtime.h>
#include <cuda_bf16.h>
#include <math.h>

#define NNODES 50000
#define EEDGES 1600000
#define BATCH  4096
#define LLMD   4096
#define HID    64
#define HEADS  8
#define OUTC   8
#define SCALE  0.35355339059327373f   // 1/sqrt(8)
#define EPS_RMS 1e-6f

// ---------------- scratch (device globals; no runtime allocation) ----------------
__device__ float g_h1 [NNODES * 128];        // after lin1+silu
__device__ float g_h  [NNODES * HID];        // node state
__device__ float g_xl [NNODES * HID];
__device__ float g_xr [NNODES * HID];
__device__ float g_agg[NNODES * HID];
__device__ float g_gx [NNODES * HID];
__device__ float g_alpha[(size_t)EEDGES * HEADS];
__device__ float g_m  [NNODES * HEADS];
__device__ float g_s  [NNODES * HEADS];
__device__ float g_cat[BATCH * 128];         // [out_g | token]
__device__ float g_f1 [BATCH * 640];
__device__ float g_f2 [BATCH * HID];

// ---------------- generic tiled fp32 GEMM: C = act(A[M,K] @ B[K,N]) ----------------
// thread grid fixed at 16x16 = 256 threads; BM/TM == BN/TN == 16.
template<int BM, int BN, int BK, int TM, int TN, bool DO_SILU>
__global__ void gemm_kernel(const float* __restrict__ A, const float* __restrict__ B,
                            float* __restrict__ C, int M, int N, int K, int ldc)
{
    __shared__ float As[BK][BM + 4];
    __shared__ float Bs[BK][BN + 4];

    const int bm = blockIdx.y * BM;
    const int bn = blockIdx.x * BN;
    const int tid = threadIdx.x;
    const int tx = tid & 15;        // col group
    const int ty = tid >> 4;        // row group

    float acc[TM][TN];
#pragma unroll
    for (int i = 0; i < TM; i++)
#pragma unroll
        for (int j = 0; j < TN; j++) acc[i][j] = 0.f;

    for (int k0 = 0; k0 < K; k0 += BK) {
        // load A tile (BM x BK), clamp rows at M edge
#pragma unroll
        for (int idx = tid; idx < BM * BK; idx += 256) {
            int m = idx / BK, k = idx % BK;
            int gm = bm + m; if (gm >= M) gm = M - 1;
            As[k][m] = A[(size_t)gm * K + k0 + k];
        }
        // load B tile (BK x BN); K % BK == 0 and N % BN == 0 for all call sites
#pragma unroll
        for (int idx = tid; idx < BK * BN; idx += 256) {
            int k = idx / BN, n = idx % BN;
            Bs[k][n] = B[(size_t)(k0 + k) * N + bn + n];
        }
        __syncthreads();

#pragma unroll
        for (int k = 0; k < BK; k++) {
            float a[TM], b[TN];
#pragma unroll
            for (int i = 0; i < TM; i++) a[i] = As[k][ty + i * 16];
#pragma unroll
            for (int j = 0; j < TN; j++) b[j] = Bs[k][tx + j * 16];
#pragma unroll
            for (int i = 0; i < TM; i++)
#pragma unroll
                for (int j = 0; j < TN; j++) acc[i][j] += a[i] * b[j];
        }
        __syncthreads();
    }

#pragma unroll
    for (int i = 0; i < TM; i++) {
        int row = bm + ty + i * 16;
        if (row >= M) continue;
#pragma unroll
        for (int j = 0; j < TN; j++) {
            float v = acc[i][j];
            if (DO_SILU) v = v / (1.f + expf(-v));
            C[(size_t)row * ldc + bn + tx + j * 16] = v;
        }
    }
}

// ---------------- row ops: out[r,0:64] = rmsnorm?(silu?(A[r,:K]@W + b)) ----------------
template<int K, bool BIAS, bool DO_SILU, bool RMS, bool GATHER>
__global__ void rowops_kernel(const float* __restrict__ A, const float* __restrict__ W,
                              const float* __restrict__ bias, const float* __restrict__ wrms,
                              const int* __restrict__ gidx,
                              float* __restrict__ C, int M, int ldc)
{
    __shared__ float Ws[K][HID];
    __shared__ float Arow[4][K];
    __shared__ float red[4][HID];

    const int tid = threadIdx.x;
    for (int i = tid; i < K * HID; i += 256) Ws[i / HID][i % HID] = W[i];
    __syncthreads();

    const int r0 = tid >> 6;          // 0..3
    const int c  = tid & 63;
    const float bv = BIAS ? bias[c] : 0.f;
    const float wv = RMS ? wrms[c] : 0.f;

    for (int rb = blockIdx.x * 4; rb < M; rb += gridDim.x * 4) {
        for (int i = tid; i < 4 * K; i += 256) {
            int r = i / K, k = i % K;
            int row = rb + r;
            float v = 0.f;
            if (row < M) {
                int arow = GATHER ? gidx[row] : row;
                v = A[(size_t)arow * K + k];
            }
            Arow[r][k] = v;
        }
        __syncthreads();

        float acc = bv;
#pragma unroll
        for (int k = 0; k < K; k++) acc += Arow[r0][k] * Ws[k][c];
        if (DO_SILU) acc = acc / (1.f + expf(-acc));

        if (RMS) {
            red[r0][c] = acc * acc;
            __syncthreads();
#pragma unroll
            for (int s = 32; s > 0; s >>= 1) {
                if (c < s) red[r0][c] += red[r0][c + s];
                __syncthreads();
            }
            float var = red[r0][0] * (1.f / 64.f);
            acc = wv * acc * rsqrtf(var + EPS_RMS);
        }
        int row = rb + r0;
        if (row < M) C[(size_t)row * ldc + c] = acc;
        __syncthreads();
    }
}

// ---------------- attention projections: xl = H@Wl+bl, xr = H@Wr+br ----------------
__global__ void attproj_kernel(const float* __restrict__ H,
                               const float* __restrict__ Wl, const float* __restrict__ bl,
                               const float* __restrict__ Wr, const float* __restrict__ br,
                               float* __restrict__ XL, float* __restrict__ XR, int M)
{
    __shared__ float Wls[HID][HID];
    __shared__ float Wrs[HID][HID];
    __shared__ float Arow[4][HID];

    const int tid = threadIdx.x;
    for (int i = tid; i < HID * HID; i += 256) {
        Wls[i / HID][i % HID] = Wl[i];
        Wrs[i / HID][i % HID] = Wr[i];
    }
    __syncthreads();

    const int r0 = tid >> 6;
    const int c  = tid & 63;
    const float bL = bl[c], bR = br[c];

    for (int rb = blockIdx.x * 4; rb < M; rb += gridDim.x * 4) {
        for (int i = tid; i < 4 * HID; i += 256) {
            int r = i / HID, k = i % HID;
            int row = rb + r;
            Arow[r][k] = (row < M) ? H[(size_t)row * HID + k] : 0.f;
        }
        __syncthreads();

        float al = bL, ar = bR;
#pragma unroll
        for (int k = 0; k < HID; k++) {
            float hv = Arow[r0][k];
            al += hv * Wls[k][c];
            ar += hv * Wrs[k][c];
        }
        int row = rb + r0;
        if (row < M) {
            XL[(size_t)row * HID + c] = al;
            XR[(size_t)row * HID + c] = ar;
        }
        __syncthreads();
    }
}

// ---------------- segment-softmax machinery ----------------
__device__ __forceinline__ void atomicMaxFloat(float* addr, float v) {
    if (v >= 0.f) atomicMax((int*)addr, __float_as_int(v));
    else          atomicMin((unsigned int*)addr, __float_as_uint(v));
}

__global__ void init_seg_kernel()
{
    for (int i = blockIdx.x * blockDim.x + threadIdx.x;
         i < NNODES * HID; i += gridDim.x * blockDim.x) {
        g_agg[i] = 0.f;
        if (i < NNODES * HEADS) { g_m[i] = -INFINITY; g_s[i] = 0.f; }
    }
}

// pass 1: alpha[e,h] = SCALE * dot8(xl[dst], xr[src]); atomicMax into m
__global__ void edge_alpha_kernel(const int* __restrict__ src, const int* __restrict__ dst)
{
    int warp = (blockIdx.x * blockDim.x + threadIdx.x) >> 5;
    int lane = threadIdx.x & 31;
    if (warp >= EEDGES) return;
    int sp = src[warp], d = dst[warp];
    const float* xi = g_xl + (size_t)d  * HID;
    const float* xj = g_xr + (size_t)sp * HID;
    float p0 = xi[lane]      * xj[lane];
    float p1 = xi[lane + 32] * xj[lane + 32];
#pragma unroll
    for (int off = 4; off; off >>= 1) {
        p0 += __shfl_down_sync(0xffffffffu, p0, off);
        p1 += __shfl_down_sync(0xffffffffu, p1, off);
    }
    if ((lane & 7) == 0) {
        int h = lane >> 3;                       // 0..3
        float a0 = p0 * SCALE, a1 = p1 * SCALE;  // heads h and h+4
        g_alpha[(size_t)warp * 8 + h]     = a0;
        g_alpha[(size_t)warp * 8 + 4 + h] = a1;
        atomicMaxFloat(&g_m[(size_t)d * 8 + h],     a0);
        atomicMaxFloat(&g_m[(size_t)d * 8 + 4 + h], a1);
    }
}

// pass 2: e = exp(alpha - m[dst]); atomicAdd into s; alpha <- e
__global__ void edge_expsum_kernel(const int* __restrict__ dst)
{
    int i = blockIdx.x * blockDim.x + threadIdx.x;
    if (i >= EEDGES * HEADS) return;
    int e = i >> 3, h = i & 7;
    int d = dst[e];
    float v = expf(g_alpha[i] - g_m[(size_t)d * 8 + h]);
    g_alpha[i] = v;
    atomicAdd(&g_s[(size_t)d * 8 + h], v);
}

// pass 3: agg[dst] += xr[src] * (e / (s[dst]+1e-16))
__global__ void edge_aggr_kernel(const int* __restrict__ src, const int* __restrict__ dst)
{
    int warp = (blockIdx.x * blockDim.x + threadIdx.x) >> 5;
    int lane = threadIdx.x & 31;
    if (warp >= EEDGES) return;
    int sp = src[warp], d = dst[warp];
    int h = lane >> 3;
    float w0 = g_alpha[(size_t)warp * 8 + h];
    float w1 = g_alpha[(size_t)warp * 8 + 4 + h];
    float s0 = g_s[(size_t)d * 8 + h];
    float s1 = g_s[(size_t)d * 8 + 4 + h];
    w0 /= (s0 + 1e-16f);
    w1 /= (s1 + 1e-16f);
    float x0 = g_xr[(size_t)sp * HID + lane];
    float x1 = g_xr[(size_t)sp * HID + lane + 32];
    atomicAdd(&g_agg[(size_t)d * HID + lane],      x0 * w0);
    atomicAdd(&g_agg[(size_t)d * HID + lane + 32], x1 * w1);
}

// ---------------- host-side launch ----------------
static inline float* sym(const void* s) {
    void* p = nullptr;
    cudaGetSymbolAddress(&p, s);
    return (float*)p;
}

extern "C" void kernel_launch(void* const* d_in, const int* in_sizes, int n_in,
                              void* d_out, int out_size)
{
    const float* x        = (const float*)d_in[0];
    const int*   eidx     = (const int*)  d_in[1];
    const int*   node_ids = (const int*)  d_in[2];
    const float* prompt   = (const float*)d_in[3];
    const float* W_lin1   = (const float*)d_in[4];
    const float* W_lin2   = (const float*)d_in[5];
    const float* w_bn1    = (const float*)d_in[6];
    const float* w_bn2    = (const float*)d_in[7];
    const float* w_bn3    = (const float*)d_in[8];
    const float* W_gnn1   = (const float*)d_in[9];
    const float* W_gnn2   = (const float*)d_in[10];
    const float* W_attl   = (const float*)d_in[11];
    const float* b_attl   = (const float*)d_in[12];
    const float* W_attr   = (const float*)d_in[13];
    const float* b_attr   = (const float*)d_in[14];
    const float* W_attl1  = (const float*)d_in[15];
    const float* b_attl1  = (const float*)d_in[16];
    const float* W_attr1  = (const float*)d_in[17];
    const float* b_attr1  = (const float*)d_in[18];
    const float* W_prompt = (const float*)d_in[19];
    const float* W_g      = (const float*)d_in[20];
    const float* W_f1     = (const float*)d_in[21];
    const float* W_f2     = (const float*)d_in[22];
    const float* W_ext    = (const float*)d_in[23];

    const int* src = eidx;
    const int* dst = eidx + EEDGES;

    float* h1  = sym(g_h1);
    float* h   = sym(g_h);
    float* xl  = sym(g_xl);
    float* xr  = sym(g_xr);
    float* agg = sym(g_agg);
    float* gx  = sym(g_gx);
    float* cat = sym(g_cat);
    float* f1  = sym(g_f1);
    float* f2  = sym(g_f2);

    const int edge_warp_blocks = (EEDGES * 32 + 255) / 256;   // 1 warp / edge
    const int edge_eh_blocks   = (EEDGES * HEADS + 255) / 256;

    // ---- GATBlock ----
    // h1 = silu(x @ W_lin1)   [50000,4096]x[4096,128]
    gemm_kernel<128,128,16,8,8,true>
        <<<dim3(1, (NNODES + 127) / 128), 256>>>(x, W_lin1, h1, NNODES, 128, LLMD, 128);
    // h = rmsnorm(h1 @ W_lin2, w_bn1)
    rowops_kernel<128,false,false,true,false>
        <<<1024, 256>>>(h1, W_lin2, nullptr, w_bn1, nullptr, h, NNODES, HID);

    // propagate 1
    attproj_kernel<<<1024, 256>>>(h, W_attl, b_attl, W_attr, b_attr, xl, xr, NNODES);
    init_seg_kernel<<<1024, 256>>>();
    edge_alpha_kernel <<<edge_warp_blocks, 256>>>(src, dst);
    edge_expsum_kernel<<<edge_eh_blocks,   256>>>(dst);
    edge_aggr_kernel  <<<edge_warp_blocks, 256>>>(src, dst);
    // h = rmsnorm(silu(agg @ W_gnn1), w_bn2)
    rowops_kernel<64,false,true,true,false>
        <<<1024, 256>>>(agg, W_gnn1, nullptr, w_bn2, nullptr, h, NNODES, HID);

    // propagate 2
    attproj_kernel<<<1024, 256>>>(h, W_attl1, b_attl1, W_attr1, b_attr1, xl, xr, NNODES);
    init_seg_kernel<<<1024, 256>>>();
    edge_alpha_kernel <<<edge_warp_blocks, 256>>>(src, dst);
    edge_expsum_kernel<<<edge_eh_blocks,   256>>>(dst);
    edge_aggr_kernel  <<<edge_warp_blocks, 256>>>(src, dst);
    // gx = rmsnorm(agg @ W_gnn2, w_bn3)
    rowops_kernel<64,false,false,true,false>
        <<<1024, 256>>>(agg, W_gnn2, nullptr, w_bn3, nullptr, gx, NNODES, HID);

    // ---- FusionBlock ----
    // cat[:,0:64]  = gx[node_ids] @ W_g
    rowops_kernel<64,false,false,false,true>
        <<<512, 256>>>(gx, W_g, nullptr, nullptr, node_ids, cat, BATCH, 128);
    // cat[:,64:128] = prompt @ W_prompt   [4096,4096]x[4096,64]
    gemm_kernel<32,64,16,2,4,false>
        <<<dim3(1, BATCH / 32), 256>>>(prompt, W_prompt, cat + 64, BATCH, 64, LLMD, 128);
    // f1 = silu(cat @ W_f1)   [4096,128]x[128,640]
    gemm_kernel<64,64,16,4,4,true>
        <<<dim3(640 / 64, BATCH / 64), 256>>>(cat, W_f1, f1, BATCH, 640, 128, 640);
    // f2 = f1 @ W_f2          [4096,640]x[640,64]
    gemm_kernel<32,64,16,2,4,false>
        <<<dim3(1, BATCH / 32), 256>>>(f1, W_f2, f2, BATCH, 64, 640, 64);
    // out = f2 @ W_ext        [4096,64]x[64,4096]
    gemm_kernel<64,64,16,4,4,false>
        <<<dim3(LLMD / 64, BATCH / 64), 256>>>(f2, W_ext, (float*)d_out, BATCH, LLMD, 64, LLMD);
}

// round 2
// speedup vs baseline: 1.6958x; 1.6958x over previous
#include <cuda_runtime.h>
#include <cuda_bf16.h>
#include <math.h>

#define NNODES 50000
#define EEDGES 1600000
#define BATCH  4096
#define LLMD   4096
#define HID    64
#define HEADS  8
#define OUTC   8
#define SCALE  0.35355339059327373f   // 1/sqrt(8)
#define EPS_RMS 1e-6f

// ---------------- scratch (device globals; no runtime allocation) ----------------
__device__ float g_h1 [NNODES * 128];        // after lin1+silu
__device__ float g_h  [NNODES * HID];        // node state
__device__ float g_xl [NNODES * HID];
__device__ float g_xr [NNODES * HID];
__device__ float g_agg[NNODES * HID];
__device__ float g_gx [NNODES * HID];
__device__ float g_alpha[(size_t)EEDGES * HEADS];
__device__ float g_m  [NNODES * HEADS];
__device__ float g_s  [NNODES * HEADS];
__device__ float g_cat[BATCH * 128];         // [out_g | token]
__device__ float g_f1 [BATCH * 640];
__device__ float g_f2 [BATCH * HID];
// bf16-split, n-major transposed W_lin1 planes: [128][4096]
__device__ __nv_bfloat16 g_Wh[(size_t)128 * LLMD];
__device__ __nv_bfloat16 g_Wl[(size_t)128 * LLMD];

// ---------------- W_lin1 -> split bf16 hi/lo, transposed to [n][k] ----------------
__global__ void convW_kernel(const float* __restrict__ W)
{
    int idx = blockIdx.x * blockDim.x + threadIdx.x;
    if (idx >= LLMD * 128) return;
    int k = idx >> 7, n = idx & 127;
    float v = W[idx];
    __nv_bfloat16 h = __float2bfloat16(v);
    float r = v - __bfloat162float(h);
    g_Wh[(size_t)n * LLMD + k] = h;
    g_Wl[(size_t)n * LLMD + k] = __float2bfloat16(r);
}

// ---------------- tensor-core GEMM: C[M,128] = silu?(A[M,K] @ W[K,128]) ----------------
// bf16 2-term split (3 mma products) => fp32-class accuracy on the tensor pipe.
__device__ __forceinline__ void mma_bf16(float* d, const unsigned* a, const unsigned* b)
{
    asm volatile(
        "mma.sync.aligned.m16n8k16.row.col.f32.bf16.bf16.f32 "
        "{%0,%1,%2,%3}, {%4,%5,%6,%7}, {%8,%9}, {%0,%1,%2,%3};\n"
        : "+f"(d[0]), "+f"(d[1]), "+f"(d[2]), "+f"(d[3])
        : "r"(a[0]), "r"(a[1]), "r"(a[2]), "r"(a[3]), "r"(b[0]), "r"(b[1]));
}

template<bool DO_SILU>
__global__ void __launch_bounds__(256, 1)
gemm_bf16s_kernel(const float* __restrict__ A,
                  const __nv_bfloat16* __restrict__ Bh,   // [128][K] n-major
                  const __nv_bfloat16* __restrict__ Bl,
                  float* __restrict__ C, int M, int K)
{
    __shared__ __nv_bfloat16 As_hi[128][34];
    __shared__ __nv_bfloat16 As_lo[128][34];
    __shared__ __nv_bfloat16 Bs_hi[128][40];
    __shared__ __nv_bfloat16 Bs_lo[128][40];

    const int tid  = threadIdx.x;
    const int lane = tid & 31;
    const int warp = tid >> 5;
    const int wm = warp & 3;        // 4 row-warps
    const int wn = warp >> 2;       // 2 col-warps
    const int row0 = wm * 32;
    const int col0 = wn * 64;
    const int bm = blockIdx.y * 128;

    float acc[2][8][4];
#pragma unroll
    for (int i = 0; i < 2; i++)
#pragma unroll
        for (int j = 0; j < 8; j++)
#pragma unroll
            for (int q = 0; q < 4; q++) acc[i][j][q] = 0.f;

    for (int kb = 0; kb < K; kb += 32) {
        // --- stage A tile (128 x 32 fp32 -> split bf16) ---
#pragma unroll
        for (int p = 0; p < 4; p++) {
            int row = (tid >> 3) + p * 32;
            int c4  = (tid & 7) * 4;
            int gr  = bm + row; if (gr >= M) gr = M - 1;
            float4 v = *reinterpret_cast<const float4*>(A + (size_t)gr * K + kb + c4);
            __nv_bfloat16 h0 = __float2bfloat16(v.x);
            __nv_bfloat16 h1 = __float2bfloat16(v.y);
            __nv_bfloat16 h2 = __float2bfloat16(v.z);
            __nv_bfloat16 h3 = __float2bfloat16(v.w);
            __nv_bfloat16 l0 = __float2bfloat16(v.x - __bfloat162float(h0));
            __nv_bfloat16 l1 = __float2bfloat16(v.y - __bfloat162float(h1));
            __nv_bfloat16 l2 = __float2bfloat16(v.z - __bfloat162float(h2));
            __nv_bfloat16 l3 = __float2bfloat16(v.w - __bfloat162float(h3));
            unsigned hp0 = ((unsigned)__bfloat16_as_ushort(h1) << 16) | __bfloat16_as_ushort(h0);
            unsigned hp1 = ((unsigned)__bfloat16_as_ushort(h3) << 16) | __bfloat16_as_ushort(h2);
            unsigned lp0 = ((unsigned)__bfloat16_as_ushort(l1) << 16) | __bfloat16_as_ushort(l0);
            unsigned lp1 = ((unsigned)__bfloat16_as_ushort(l3) << 16) | __bfloat16_as_ushort(l2);
            *reinterpret_cast<unsigned*>(&As_hi[row][c4])     = hp0;
            *reinterpret_cast<unsigned*>(&As_hi[row][c4 + 2]) = hp1;
            *reinterpret_cast<unsigned*>(&As_lo[row][c4])     = lp0;
            *reinterpret_cast<unsigned*>(&As_lo[row][c4 + 2]) = lp1;
        }
        // --- stage B tile (contiguous copy from pre-transposed planes) ---
#pragma unroll
        for (int q = 0; q < 2; q++) {
            int lin = tid + q * 256;           // 0..511
            int n   = lin >> 2;
            int k8  = (lin & 3) * 8;
            *reinterpret_cast<uint4*>(&Bs_hi[n][k8]) =
                *reinterpret_cast<const uint4*>(Bh + (size_t)n * K + kb + k8);
            *reinterpret_cast<uint4*>(&Bs_lo[n][k8]) =
                *reinterpret_cast<const uint4*>(Bl + (size_t)n * K + kb + k8);
        }
        __syncthreads();

#pragma unroll
        for (int ks = 0; ks < 32; ks += 16) {
            const int ac = ks + (lane & 3) * 2;
            const int ar = row0 + (lane >> 2);
            unsigned Ah[2][4], Al[2][4];
#pragma unroll
            for (int mt = 0; mt < 2; mt++) {
                int r = ar + mt * 16;
                Ah[mt][0] = *reinterpret_cast<const unsigned*>(&As_hi[r][ac]);
                Ah[mt][1] = *reinterpret_cast<const unsigned*>(&As_hi[r + 8][ac]);
                Ah[mt][2] = *reinterpret_cast<const unsigned*>(&As_hi[r][ac + 8]);
                Ah[mt][3] = *reinterpret_cast<const unsigned*>(&As_hi[r + 8][ac + 8]);
                Al[mt][0] = *reinterpret_cast<const unsigned*>(&As_lo[r][ac]);
                Al[mt][1] = *reinterpret_cast<const unsigned*>(&As_lo[r + 8][ac]);
                Al[mt][2] = *reinterpret_cast<const unsigned*>(&As_lo[r][ac + 8]);
                Al[mt][3] = *reinterpret_cast<const unsigned*>(&As_lo[r + 8][ac + 8]);
            }
#pragma unroll
            for (int nt = 0; nt < 8; nt++) {
                int n = col0 + nt * 8 + (lane >> 2);
                unsigned Bh2[2], Bl2[2];
                Bh2[0] = *reinterpret_cast<const unsigned*>(&Bs_hi[n][ac]);
                Bh2[1] = *reinterpret_cast<const unsigned*>(&Bs_hi[n][ac + 8]);
                Bl2[0] = *reinterpret_cast<const unsigned*>(&Bs_lo[n][ac]);
                Bl2[1] = *reinterpret_cast<const unsigned*>(&Bs_lo[n][ac + 8]);
#pragma unroll
                for (int mt = 0; mt < 2; mt++) {
                    mma_bf16(acc[mt][nt], Ah[mt], Bh2);
                    mma_bf16(acc[mt][nt], Ah[mt], Bl2);
                    mma_bf16(acc[mt][nt], Al[mt], Bh2);
                }
            }
        }
        __syncthreads();
    }

    // --- epilogue ---
#pragma unroll
    for (int mt = 0; mt < 2; mt++) {
#pragma unroll
        for (int nt = 0; nt < 8; nt++) {
            int r  = bm + row0 + mt * 16 + (lane >> 2);
            int cc = col0 + nt * 8 + (lane & 3) * 2;
            float v0 = acc[mt][nt][0], v1 = acc[mt][nt][1];
            float v2 = acc[mt][nt][2], v3 = acc[mt][nt][3];
            if (DO_SILU) {
                v0 = v0 / (1.f + expf(-v0)); v1 = v1 / (1.f + expf(-v1));
                v2 = v2 / (1.f + expf(-v2)); v3 = v3 / (1.f + expf(-v3));
            }
            if (r < M)     { float2 w = {v0, v1}; *reinterpret_cast<float2*>(&C[(size_t)r * 128 + cc]) = w; }
            if (r + 8 < M) { float2 w = {v2, v3}; *reinterpret_cast<float2*>(&C[(size_t)(r + 8) * 128 + cc]) = w; }
        }
    }
}

// ---------------- generic tiled fp32 GEMM: C = act(A[M,K] @ B[K,N]) ----------------
template<int BM, int BN, int BK, int TM, int TN, bool DO_SILU>
__global__ void gemm_kernel(const float* __restrict__ A, const float* __restrict__ B,
                            float* __restrict__ C, int M, int N, int K, int ldc)
{
    __shared__ float As[BK][BM + 4];
    __shared__ float Bs[BK][BN + 4];

    const int bm = blockIdx.y * BM;
    const int bn = blockIdx.x * BN;
    const int tid = threadIdx.x;
    const int tx = tid & 15;
    const int ty = tid >> 4;

    float acc[TM][TN];
#pragma unroll
    for (int i = 0; i < TM; i++)
#pragma unroll
        for (int j = 0; j < TN; j++) acc[i][j] = 0.f;

    for (int k0 = 0; k0 < K; k0 += BK) {
#pragma unroll
        for (int idx = tid; idx < BM * BK; idx += 256) {
            int m = idx / BK, k = idx % BK;
            int gm = bm + m; if (gm >= M) gm = M - 1;
            As[k][m] = A[(size_t)gm * K + k0 + k];
        }
#pragma unroll
        for (int idx = tid; idx < BK * BN; idx += 256) {
            int k = idx / BN, n = idx % BN;
            Bs[k][n] = B[(size_t)(k0 + k) * N + bn + n];
        }
        __syncthreads();

#pragma unroll
        for (int k = 0; k < BK; k++) {
            float a[TM], b[TN];
#pragma unroll
            for (int i = 0; i < TM; i++) a[i] = As[k][ty + i * 16];
#pragma unroll
            for (int j = 0; j < TN; j++) b[j] = Bs[k][tx + j * 16];
#pragma unroll
            for (int i = 0; i < TM; i++)
#pragma unroll
                for (int j = 0; j < TN; j++) acc[i][j] += a[i] * b[j];
        }
        __syncthreads();
    }

#pragma unroll
    for (int i = 0; i < TM; i++) {
        int row = bm + ty + i * 16;
        if (row >= M) continue;
#pragma unroll
        for (int j = 0; j < TN; j++) {
            float v = acc[i][j];
            if (DO_SILU) v = v / (1.f + expf(-v));
            C[(size_t)row * ldc + bn + tx + j * 16] = v;
        }
    }
}

// ---------------- row ops: out[r,0:64] = rmsnorm?(silu?(A[r,:K]@W + b)) ----------------
template<int K, bool BIAS, bool DO_SILU, bool RMS, bool GATHER>
__global__ void rowops_kernel(const float* __restrict__ A, const float* __restrict__ W,
                              const float* __restrict__ bias, const float* __restrict__ wrms,
                              const int* __restrict__ gidx,
                              float* __restrict__ C, int M, int ldc)
{
    __shared__ float Ws[K][HID];
    __shared__ float Arow[4][K];
    __shared__ float red[4][HID];

    const int tid = threadIdx.x;
    for (int i = tid; i < K * HID; i += 256) Ws[i / HID][i % HID] = W[i];
    __syncthreads();

    const int r0 = tid >> 6;
    const int c  = tid & 63;
    const float bv = BIAS ? bias[c] : 0.f;
    const float wv = RMS ? wrms[c] : 0.f;

    for (int rb = blockIdx.x * 4; rb < M; rb += gridDim.x * 4) {
        for (int i = tid; i < 4 * K; i += 256) {
            int r = i / K, k = i % K;
            int row = rb + r;
            float v = 0.f;
            if (row < M) {
                int arow = GATHER ? gidx[row] : row;
                v = A[(size_t)arow * K + k];
            }
            Arow[r][k] = v;
        }
        __syncthreads();

        float acc = bv;
#pragma unroll
        for (int k = 0; k < K; k++) acc += Arow[r0][k] * Ws[k][c];
        if (DO_SILU) acc = acc / (1.f + expf(-acc));

        if (RMS) {
            red[r0][c] = acc * acc;
            __syncthreads();
#pragma unroll
            for (int s = 32; s > 0; s >>= 1) {
                if (c < s) red[r0][c] += red[r0][c + s];
                __syncthreads();
            }
            float var = red[r0][0] * (1.f / 64.f);
            acc = wv * acc * rsqrtf(var + EPS_RMS);
        }
        int row = rb + r0;
        if (row < M) C[(size_t)row * ldc + c] = acc;
        __syncthreads();
    }
}

// ---------------- attention projections: xl = H@Wl+bl, xr = H@Wr+br ----------------
__global__ void attproj_kernel(const float* __restrict__ H,
                               const float* __restrict__ Wl, const float* __restrict__ bl,
                               const float* __restrict__ Wr, const float* __restrict__ br,
                               float* __restrict__ XL, float* __restrict__ XR, int M)
{
    __shared__ float Wls[HID][HID];
    __shared__ float Wrs[HID][HID];
    __shared__ float Arow[4][HID];

    const int tid = threadIdx.x;
    for (int i = tid; i < HID * HID; i += 256) {
        Wls[i / HID][i % HID] = Wl[i];
        Wrs[i / HID][i % HID] = Wr[i];
    }
    __syncthreads();

    const int r0 = tid >> 6;
    const int c  = tid & 63;
    const float bL = bl[c], bR = br[c];

    for (int rb = blockIdx.x * 4; rb < M; rb += gridDim.x * 4) {
        for (int i = tid; i < 4 * HID; i += 256) {
            int r = i / HID, k = i % HID;
            int row = rb + r;
            Arow[r][k] = (row < M) ? H[(size_t)row * HID + k] : 0.f;
        }
        __syncthreads();

        float al = bL, ar = bR;
#pragma unroll
        for (int k = 0; k < HID; k++) {
            float hv = Arow[r0][k];
            al += hv * Wls[k][c];
            ar += hv * Wrs[k][c];
        }
        int row = rb + r0;
        if (row < M) {
            XL[(size_t)row * HID + c] = al;
            XR[(size_t)row * HID + c] = ar;
        }
        __syncthreads();
    }
}

// ---------------- segment-softmax machinery ----------------
__device__ __forceinline__ void atomicMaxFloat(float* addr, float v) {
    if (v >= 0.f) atomicMax((int*)addr, __float_as_int(v));
    else          atomicMin((unsigned int*)addr, __float_as_uint(v));
}

__global__ void init_seg_kernel()
{
    for (int i = blockIdx.x * blockDim.x + threadIdx.x;
         i < NNODES * HID; i += gridDim.x * blockDim.x) {
        g_agg[i] = 0.f;
        if (i < NNODES * HEADS) { g_m[i] = -INFINITY; g_s[i] = 0.f; }
    }
}

// pass 1: alpha[e,h] = SCALE * dot8(xl[dst], xr[src]); atomicMax into m
__global__ void edge_alpha_kernel(const int* __restrict__ src, const int* __restrict__ dst)
{
    int warp = (blockIdx.x * blockDim.x + threadIdx.x) >> 5;
    int lane = threadIdx.x & 31;
    if (warp >= EEDGES) return;
    int sp = src[warp], d = dst[warp];
    const float* xi = g_xl + (size_t)d  * HID;
    const float* xj = g_xr + (size_t)sp * HID;
    float p0 = xi[lane]      * xj[lane];
    float p1 = xi[lane + 32] * xj[lane + 32];
#pragma unroll
    for (int off = 4; off; off >>= 1) {
        p0 += __shfl_down_sync(0xffffffffu, p0, off);
        p1 += __shfl_down_sync(0xffffffffu, p1, off);
    }
    if ((lane & 7) == 0) {
        int h = lane >> 3;
        float a0 = p0 * SCALE, a1 = p1 * SCALE;
        g_alpha[(size_t)warp * 8 + h]     = a0;
        g_alpha[(size_t)warp * 8 + 4 + h] = a1;
        atomicMaxFloat(&g_m[(size_t)d * 8 + h],     a0);
        atomicMaxFloat(&g_m[(size_t)d * 8 + 4 + h], a1);
    }
}

// pass 2: e = exp(alpha - m[dst]); atomicAdd into s; alpha <- e
__global__ void edge_expsum_kernel(const int* __restrict__ dst)
{
    int i = blockIdx.x * blockDim.x + threadIdx.x;
    if (i >= EEDGES * HEADS) return;
    int e = i >> 3, h = i & 7;
    int d = dst[e];
    float v = expf(g_alpha[i] - g_m[(size_t)d * 8 + h]);
    g_alpha[i] = v;
    atomicAdd(&g_s[(size_t)d * 8 + h], v);
}

// pass 3: agg[dst] += xr[src] * (e / (s[dst]+1e-16))
__global__ void edge_aggr_kernel(const int* __restrict__ src, const int* __restrict__ dst)
{
    int warp = (blockIdx.x * blockDim.x + threadIdx.x) >> 5;
    int lane = threadIdx.x & 31;
    if (warp >= EEDGES) return;
    int sp = src[warp], d = dst[warp];
    int h = lane >> 3;
    float w0 = g_alpha[(size_t)warp * 8 + h];
    float w1 = g_alpha[(size_t)warp * 8 + 4 + h];
    float s0 = g_s[(size_t)d * 8 + h];
    float s1 = g_s[(size_t)d * 8 + 4 + h];
    w0 /= (s0 + 1e-16f);
    w1 /= (s1 + 1e-16f);
    float x0 = g_xr[(size_t)sp * HID + lane];
    float x1 = g_xr[(size_t)sp * HID + lane + 32];
    atomicAdd(&g_agg[(size_t)d * HID + lane],      x0 * w0);
    atomicAdd(&g_agg[(size_t)d * HID + lane + 32], x1 * w1);
}

// ---------------- host-side launch ----------------
static inline void* symv(const void* s) {
    void* p = nullptr;
    cudaGetSymbolAddress(&p, s);
    return p;
}

extern "C" void kernel_launch(void* const* d_in, const int* in_sizes, int n_in,
                              void* d_out, int out_size)
{
    const float* x        = (const float*)d_in[0];
    const int*   eidx     = (const int*)  d_in[1];
    const int*   node_ids = (const int*)  d_in[2];
    const float* prompt   = (const float*)d_in[3];
    const float* W_lin1   = (const float*)d_in[4];
    const float* W_lin2   = (const float*)d_in[5];
    const float* w_bn1    = (const float*)d_in[6];
    const float* w_bn2    = (const float*)d_in[7];
    const float* w_bn3    = (const float*)d_in[8];
    const float* W_gnn1   = (const float*)d_in[9];
    const float* W_gnn2   = (const float*)d_in[10];
    const float* W_attl   = (const float*)d_in[11];
    const float* b_attl   = (const float*)d_in[12];
    const float* W_attr   = (const float*)d_in[13];
    const float* b_attr   = (const float*)d_in[14];
    const float* W_attl1  = (const float*)d_in[15];
    const float* b_attl1  = (const float*)d_in[16];
    const float* W_attr1  = (const float*)d_in[17];
    const float* b_attr1  = (const float*)d_in[18];
    const float* W_prompt = (const float*)d_in[19];
    const float* W_g      = (const float*)d_in[20];
    const float* W_f1     = (const float*)d_in[21];
    const float* W_f2     = (const float*)d_in[22];
    const float* W_ext    = (const float*)d_in[23];

    const int* src = eidx;
    const int* dst = eidx + EEDGES;

    float* h1  = (float*)symv(g_h1);
    float* h   = (float*)symv(g_h);
    float* xl  = (float*)symv(g_xl);
    float* xr  = (float*)symv(g_xr);
    float* agg = (float*)symv(g_agg);
    float* gx  = (float*)symv(g_gx);
    float* cat = (float*)symv(g_cat);
    float* f1  = (float*)symv(g_f1);
    float* f2  = (float*)symv(g_f2);
    __nv_bfloat16* Wh = (__nv_bfloat16*)symv(g_Wh);
    __nv_bfloat16* Wl = (__nv_bfloat16*)symv(g_Wl);

    const int edge_warp_blocks = (EEDGES * 32 + 255) / 256;
    const int edge_eh_blocks   = (EEDGES * HEADS + 255) / 256;

    // ---- GATBlock ----
    // split/transpose W_lin1 once, then tensor-core GEMM: h1 = silu(x @ W_lin1)
    convW_kernel<<<(LLMD * 128 + 511) / 512, 512>>>(W_lin1);
    gemm_bf16s_kernel<true>
        <<<dim3(1, (NNODES + 127) / 128), 256>>>(x, Wh, Wl, h1, NNODES, LLMD);
    // h = rmsnorm(h1 @ W_lin2, w_bn1)
    rowops_kernel<128,false,false,true,false>
        <<<1024, 256>>>(h1, W_lin2, nullptr, w_bn1, nullptr, h, NNODES, HID);

    // propagate 1
    attproj_kernel<<<1024, 256>>>(h, W_attl, b_attl, W_attr, b_attr, xl, xr, NNODES);
    init_seg_kernel<<<1024, 256>>>();
    edge_alpha_kernel <<<edge_warp_blocks, 256>>>(src, dst);
    edge_expsum_kernel<<<edge_eh_blocks,   256>>>(dst);
    edge_aggr_kernel  <<<edge_warp_blocks, 256>>>(src, dst);
    // h = rmsnorm(silu(agg @ W_gnn1), w_bn2)
    rowops_kernel<64,false,true,true,false>
        <<<1024, 256>>>(agg, W_gnn1, nullptr, w_bn2, nullptr, h, NNODES, HID);

    // propagate 2
    attproj_kernel<<<1024, 256>>>(h, W_attl1, b_attl1, W_attr1, b_attr1, xl, xr, NNODES);
    init_seg_kernel<<<1024, 256>>>();
    edge_alpha_kernel <<<edge_warp_blocks, 256>>>(src, dst);
    edge_expsum_kernel<<<edge_eh_blocks,   256>>>(dst);
    edge_aggr_kernel  <<<edge_warp_blocks, 256>>>(src, dst);
    // gx = rmsnorm(agg @ W_gnn2, w_bn3)
    rowops_kernel<64,false,false,true,false>
        <<<1024, 256>>>(agg, W_gnn2, nullptr, w_bn3, nullptr, gx, NNODES, HID);

    // ---- FusionBlock ----
    rowops_kernel<64,false,false,false,true>
        <<<512, 256>>>(gx, W_g, nullptr, nullptr, node_ids, cat, BATCH, 128);
    gemm_kernel<32,64,16,2,4,false>
        <<<dim3(1, BATCH / 32), 256>>>(prompt, W_prompt, cat + 64, BATCH, 64, LLMD, 128);
    gemm_kernel<64,64,16,4,4,true>
        <<<dim3(640 / 64, BATCH / 64), 256>>>(cat, W_f1, f1, BATCH, 640, 128, 640);
    gemm_kernel<32,64,16,2,4,false>
        <<<dim3(1, BATCH / 32), 256>>>(f1, W_f2, f2, BATCH, 64, 640, 64);
    gemm_kernel<64,64,16,4,4,false>
        <<<dim3(LLMD / 64, BATCH / 64), 256>>>(f2, W_ext, (float*)d_out, BATCH, LLMD, 64, LLMD);
}

// round 3
// speedup vs baseline: 1.9960x; 1.1771x over previous
#include <cuda_runtime.h>
#include <cuda_bf16.h>
#include <math.h>

#define NNODES 50000
#define EEDGES 1600000
#define BATCH  4096
#define LLMD   4096
#define HID    64
#define HEADS  8
#define SCALE  0.35355339059327373f   // 1/sqrt(8)
#define EPS_RMS 1e-6f

// ---------------- scratch (device globals; no runtime allocation) ----------------
__device__ float g_h1 [NNODES * 128];
__device__ float g_h  [NNODES * HID];
__device__ float g_xl [NNODES * HID];
__device__ float g_xr [NNODES * HID];
__device__ float g_agg[NNODES * HID];
__device__ float g_gx [NNODES * HID];
__device__ float g_alpha[(size_t)EEDGES * HEADS];
__device__ float g_s  [NNODES * HEADS];
__device__ float g_cat[BATCH * 128];
__device__ float g_f1 [BATCH * 640];
__device__ float g_f2 [BATCH * HID];
// bf16-split, n-major transposed weight planes
__device__ __nv_bfloat16 g_Wh[(size_t)128 * LLMD];
__device__ __nv_bfloat16 g_Wl[(size_t)128 * LLMD];
__device__ __nv_bfloat16 g_Ph[(size_t)64 * LLMD];
__device__ __nv_bfloat16 g_Pl[(size_t)64 * LLMD];

// ---------------- W[k][n] -> split bf16 hi/lo, transposed to [n][k] ----------------
__global__ void conv_split_kernel(const float* __restrict__ W,
                                  __nv_bfloat16* __restrict__ H,
                                  __nv_bfloat16* __restrict__ L, int N, int K)
{
    int idx = blockIdx.x * blockDim.x + threadIdx.x;
    if (idx >= N * K) return;
    int k = idx / N, n = idx % N;
    float v = W[idx];
    __nv_bfloat16 h = __float2bfloat16(v);
    float r = v - __bfloat162float(h);
    H[(size_t)n * K + k] = h;
    L[(size_t)n * K + k] = __float2bfloat16(r);
}

// ---------------- tensor-core GEMM: C[M,16*NT] = silu?(A[M,K] @ W) ----------------
__device__ __forceinline__ void mma_bf16(float* d, const unsigned* a, const unsigned* b)
{
    asm volatile(
        "mma.sync.aligned.m16n8k16.row.col.f32.bf16.bf16.f32 "
        "{%0,%1,%2,%3}, {%4,%5,%6,%7}, {%8,%9}, {%0,%1,%2,%3};\n"
        : "+f"(d[0]), "+f"(d[1]), "+f"(d[2]), "+f"(d[3])
        : "r"(a[0]), "r"(a[1]), "r"(a[2]), "r"(a[3]), "r"(b[0]), "r"(b[1]));
}

template<int NT, bool DO_SILU>   // output cols = 16*NT (2 col-warps x NT x 8)
__global__ void __launch_bounds__(256, 1)
gemm_bf16s_kernel(const float* __restrict__ A,
                  const __nv_bfloat16* __restrict__ Bh,   // [NCOLS][K] n-major
                  const __nv_bfloat16* __restrict__ Bl,
                  float* __restrict__ C, int M, int K, int ldc)
{
    constexpr int NC = 16 * NT;
    __shared__ __nv_bfloat16 As_hi[128][34];
    __shared__ __nv_bfloat16 As_lo[128][34];
    __shared__ __nv_bfloat16 Bs_hi[NC][40];
    __shared__ __nv_bfloat16 Bs_lo[NC][40];

    const int tid  = threadIdx.x;
    const int lane = tid & 31;
    const int warp = tid >> 5;
    const int wm = warp & 3;
    const int wn = warp >> 2;
    const int row0 = wm * 32;
    const int col0 = wn * (NT * 8);
    const int bm = blockIdx.y * 128;

    float acc[2][NT][4];
#pragma unroll
    for (int i = 0; i < 2; i++)
#pragma unroll
        for (int j = 0; j < NT; j++)
#pragma unroll
            for (int q = 0; q < 4; q++) acc[i][j][q] = 0.f;

    for (int kb = 0; kb < K; kb += 32) {
#pragma unroll
        for (int p = 0; p < 4; p++) {
            int row = (tid >> 3) + p * 32;
            int c4  = (tid & 7) * 4;
            int gr  = bm + row; if (gr >= M) gr = M - 1;
            float4 v = *reinterpret_cast<const float4*>(A + (size_t)gr * K + kb + c4);
            __nv_bfloat16 h0 = __float2bfloat16(v.x);
            __nv_bfloat16 h1 = __float2bfloat16(v.y);
            __nv_bfloat16 h2 = __float2bfloat16(v.z);
            __nv_bfloat16 h3 = __float2bfloat16(v.w);
            __nv_bfloat16 l0 = __float2bfloat16(v.x - __bfloat162float(h0));
            __nv_bfloat16 l1 = __float2bfloat16(v.y - __bfloat162float(h1));
            __nv_bfloat16 l2 = __float2bfloat16(v.z - __bfloat162float(h2));
            __nv_bfloat16 l3 = __float2bfloat16(v.w - __bfloat162float(h3));
            unsigned hp0 = ((unsigned)__bfloat16_as_ushort(h1) << 16) | __bfloat16_as_ushort(h0);
            unsigned hp1 = ((unsigned)__bfloat16_as_ushort(h3) << 16) | __bfloat16_as_ushort(h2);
            unsigned lp0 = ((unsigned)__bfloat16_as_ushort(l1) << 16) | __bfloat16_as_ushort(l0);
            unsigned lp1 = ((unsigned)__bfloat16_as_ushort(l3) << 16) | __bfloat16_as_ushort(l2);
            *reinterpret_cast<unsigned*>(&As_hi[row][c4])     = hp0;
            *reinterpret_cast<unsigned*>(&As_hi[row][c4 + 2]) = hp1;
            *reinterpret_cast<unsigned*>(&As_lo[row][c4])     = lp0;
            *reinterpret_cast<unsigned*>(&As_lo[row][c4 + 2]) = lp1;
        }
#pragma unroll
        for (int lin = tid; lin < NC * 4; lin += 256) {
            int n  = lin >> 2;
            int k8 = (lin & 3) * 8;
            *reinterpret_cast<uint4*>(&Bs_hi[n][k8]) =
                *reinterpret_cast<const uint4*>(Bh + (size_t)n * K + kb + k8);
            *reinterpret_cast<uint4*>(&Bs_lo[n][k8]) =
                *reinterpret_cast<const uint4*>(Bl + (size_t)n * K + kb + k8);
        }
        __syncthreads();

#pragma unroll
        for (int ks = 0; ks < 32; ks += 16) {
            const int ac = ks + (lane & 3) * 2;
            const int ar = row0 + (lane >> 2);
            unsigned Ah[2][4], Al[2][4];
#pragma unroll
            for (int mt = 0; mt < 2; mt++) {
                int r = ar + mt * 16;
                Ah[mt][0] = *reinterpret_cast<const unsigned*>(&As_hi[r][ac]);
                Ah[mt][1] = *reinterpret_cast<const unsigned*>(&As_hi[r + 8][ac]);
                Ah[mt][2] = *reinterpret_cast<const unsigned*>(&As_hi[r][ac + 8]);
                Ah[mt][3] = *reinterpret_cast<const unsigned*>(&As_hi[r + 8][ac + 8]);
                Al[mt][0] = *reinterpret_cast<const unsigned*>(&As_lo[r][ac]);
                Al[mt][1] = *reinterpret_cast<const unsigned*>(&As_lo[r + 8][ac]);
                Al[mt][2] = *reinterpret_cast<const unsigned*>(&As_lo[r][ac + 8]);
                Al[mt][3] = *reinterpret_cast<const unsigned*>(&As_lo[r + 8][ac + 8]);
            }
#pragma unroll
            for (int nt = 0; nt < NT; nt++) {
                int n = col0 + nt * 8 + (lane >> 2);
                unsigned Bh2[2], Bl2[2];
                Bh2[0] = *reinterpret_cast<const unsigned*>(&Bs_hi[n][ac]);
                Bh2[1] = *reinterpret_cast<const unsigned*>(&Bs_hi[n][ac + 8]);
                Bl2[0] = *reinterpret_cast<const unsigned*>(&Bs_lo[n][ac]);
                Bl2[1] = *reinterpret_cast<const unsigned*>(&Bs_lo[n][ac + 8]);
#pragma unroll
                for (int mt = 0; mt < 2; mt++) {
                    mma_bf16(acc[mt][nt], Ah[mt], Bh2);
                    mma_bf16(acc[mt][nt], Ah[mt], Bl2);
                    mma_bf16(acc[mt][nt], Al[mt], Bh2);
                }
            }
        }
        __syncthreads();
    }

#pragma unroll
    for (int mt = 0; mt < 2; mt++) {
#pragma unroll
        for (int nt = 0; nt < NT; nt++) {
            int r  = bm + row0 + mt * 16 + (lane >> 2);
            int cc = col0 + nt * 8 + (lane & 3) * 2;
            float v0 = acc[mt][nt][0], v1 = acc[mt][nt][1];
            float v2 = acc[mt][nt][2], v3 = acc[mt][nt][3];
            if (DO_SILU) {
                v0 = v0 / (1.f + expf(-v0)); v1 = v1 / (1.f + expf(-v1));
                v2 = v2 / (1.f + expf(-v2)); v3 = v3 / (1.f + expf(-v3));
            }
            if (r < M)     { float2 w = {v0, v1}; *reinterpret_cast<float2*>(&C[(size_t)r * ldc + cc]) = w; }
            if (r + 8 < M) { float2 w = {v2, v3}; *reinterpret_cast<float2*>(&C[(size_t)(r + 8) * ldc + cc]) = w; }
        }
    }
}

// ---------------- generic tiled fp32 GEMM (fusion tail) ----------------
template<int BM, int BN, int BK, int TM, int TN, bool DO_SILU>
__global__ void gemm_kernel(const float* __restrict__ A, const float* __restrict__ B,
                            float* __restrict__ C, int M, int N, int K, int ldc)
{
    __shared__ float As[BK][BM + 4];
    __shared__ float Bs[BK][BN + 4];

    const int bm = blockIdx.y * BM;
    const int bn = blockIdx.x * BN;
    const int tid = threadIdx.x;
    const int tx = tid & 15;
    const int ty = tid >> 4;

    float acc[TM][TN];
#pragma unroll
    for (int i = 0; i < TM; i++)
#pragma unroll
        for (int j = 0; j < TN; j++) acc[i][j] = 0.f;

    for (int k0 = 0; k0 < K; k0 += BK) {
#pragma unroll
        for (int idx = tid; idx < BM * BK; idx += 256) {
            int m = idx / BK, k = idx % BK;
            int gm = bm + m; if (gm >= M) gm = M - 1;
            As[k][m] = A[(size_t)gm * K + k0 + k];
        }
#pragma unroll
        for (int idx = tid; idx < BK * BN; idx += 256) {
            int k = idx / BN, n = idx % BN;
            Bs[k][n] = B[(size_t)(k0 + k) * N + bn + n];
        }
        __syncthreads();

#pragma unroll
        for (int k = 0; k < BK; k++) {
            float a[TM], b[TN];
#pragma unroll
            for (int i = 0; i < TM; i++) a[i] = As[k][ty + i * 16];
#pragma unroll
            for (int j = 0; j < TN; j++) b[j] = Bs[k][tx + j * 16];
#pragma unroll
            for (int i = 0; i < TM; i++)
#pragma unroll
                for (int j = 0; j < TN; j++) acc[i][j] += a[i] * b[j];
        }
        __syncthreads();
    }

#pragma unroll
    for (int i = 0; i < TM; i++) {
        int row = bm + ty + i * 16;
        if (row >= M) continue;
#pragma unroll
        for (int j = 0; j < TN; j++) {
            float v = acc[i][j];
            if (DO_SILU) v = v / (1.f + expf(-v));
            C[(size_t)row * ldc + bn + tx + j * 16] = v;
        }
    }
}

// ---------------- row ops (float4): out[r,0:64] = rms?(silu?(A[r,:K]@W)) ----------------
// 256 threads: warp = 2 rows (16 lanes each), lane covers 4 cols. 16 rows/iter.
template<int K, bool DO_SILU, bool RMS, bool GATHER>
__global__ void rowops_kernel(const float* __restrict__ A, const float* __restrict__ W,
                              const float* __restrict__ wrms, const int* __restrict__ gidx,
                              float* __restrict__ C, int M, int ldc)
{
    __shared__ float Ws[K][HID];
    __shared__ float Arow[16][K];

    const int tid = threadIdx.x;
    for (int i = tid; i < K * HID / 4; i += 256)
        *reinterpret_cast<float4*>(&Ws[0][0] + i * 4) =
            *reinterpret_cast<const float4*>(W + i * 4);
    __syncthreads();

    const int lane = tid & 31;
    const int r    = (tid >> 5) * 2 + (lane >> 4);   // 0..15
    const int c4   = (lane & 15) * 4;
    float4 wv = {1.f, 1.f, 1.f, 1.f};
    if (RMS) wv = *reinterpret_cast<const float4*>(wrms + c4);

    for (int rb = blockIdx.x * 16; rb < M; rb += gridDim.x * 16) {
        for (int i = tid; i < 16 * K / 4; i += 256) {
            int rr = (i * 4) / K, kk = (i * 4) % K;
            int row = rb + rr; if (row >= M) row = M - 1;
            int arow = GATHER ? gidx[row] : row;
            *reinterpret_cast<float4*>(&Arow[rr][kk]) =
                *reinterpret_cast<const float4*>(A + (size_t)arow * K + kk);
        }
        __syncthreads();

        float4 acc = {0.f, 0.f, 0.f, 0.f};
#pragma unroll
        for (int k = 0; k < K; k += 4) {
            float4 a4 = *reinterpret_cast<const float4*>(&Arow[r][k]);
            float4 w0 = *reinterpret_cast<const float4*>(&Ws[k][c4]);
            float4 w1 = *reinterpret_cast<const float4*>(&Ws[k + 1][c4]);
            float4 w2 = *reinterpret_cast<const float4*>(&Ws[k + 2][c4]);
            float4 w3 = *reinterpret_cast<const float4*>(&Ws[k + 3][c4]);
            acc.x += a4.x * w0.x + a4.y * w1.x + a4.z * w2.x + a4.w * w3.x;
            acc.y += a4.x * w0.y + a4.y * w1.y + a4.z * w2.y + a4.w * w3.y;
            acc.z += a4.x * w0.z + a4.y * w1.z + a4.z * w2.z + a4.w * w3.z;
            acc.w += a4.x * w0.w + a4.y * w1.w + a4.z * w2.w + a4.w * w3.w;
        }
        if (DO_SILU) {
            acc.x = acc.x / (1.f + expf(-acc.x));
            acc.y = acc.y / (1.f + expf(-acc.y));
            acc.z = acc.z / (1.f + expf(-acc.z));
            acc.w = acc.w / (1.f + expf(-acc.w));
        }
        if (RMS) {
            float ss = acc.x * acc.x + acc.y * acc.y + acc.z * acc.z + acc.w * acc.w;
#pragma unroll
            for (int off = 8; off; off >>= 1)
                ss += __shfl_xor_sync(0xffffffffu, ss, off);
            float sc = rsqrtf(ss * (1.f / 64.f) + EPS_RMS);
            acc.x *= wv.x * sc; acc.y *= wv.y * sc;
            acc.z *= wv.z * sc; acc.w *= wv.w * sc;
        }
        int row = rb + r;
        if (row < M) *reinterpret_cast<float4*>(&C[(size_t)row * ldc + c4]) = acc;
        __syncthreads();
    }
}

// ---------------- attention projections (float4): xl=H@Wl+bl, xr=H@Wr+br ----------------
// 256 threads: warp = 1 row; lanes 0-15 -> xl cols, lanes 16-31 -> xr cols. 8 rows/iter.
__global__ void attproj_kernel(const float* __restrict__ H,
                               const float* __restrict__ Wl, const float* __restrict__ bl,
                               const float* __restrict__ Wr, const float* __restrict__ br,
                               float* __restrict__ XL, float* __restrict__ XR, int M)
{
    __shared__ float Wls[HID][HID];
    __shared__ float Wrs[HID][HID];
    __shared__ float Arow[8][HID];

    const int tid = threadIdx.x;
    for (int i = tid; i < HID * HID / 4; i += 256) {
        *reinterpret_cast<float4*>(&Wls[0][0] + i * 4) =
            *reinterpret_cast<const float4*>(Wl + i * 4);
        *reinterpret_cast<float4*>(&Wrs[0][0] + i * 4) =
            *reinterpret_cast<const float4*>(Wr + i * 4);
    }
    __syncthreads();

    const int lane = tid & 31;
    const int r    = tid >> 5;               // 0..7
    const bool isR = lane >= 16;
    const int c4   = (lane & 15) * 4;
    const float* Wcol = isR ? &Wrs[0][0] : &Wls[0][0];
    float4 bias = *reinterpret_cast<const float4*>((isR ? br : bl) + c4);
    float* OUT = isR ? XR : XL;

    for (int rb = blockIdx.x * 8; rb < M; rb += gridDim.x * 8) {
        for (int i = tid; i < 8 * HID / 4; i += 256) {
            int rr = (i * 4) / HID, kk = (i * 4) % HID;
            int row = rb + rr; if (row >= M) row = M - 1;
            *reinterpret_cast<float4*>(&Arow[rr][kk]) =
                *reinterpret_cast<const float4*>(H + (size_t)row * HID + kk);
        }
        __syncthreads();

        float4 acc = bias;
#pragma unroll
        for (int k = 0; k < HID; k += 4) {
            float4 a4 = *reinterpret_cast<const float4*>(&Arow[r][k]);
            float4 w0 = *reinterpret_cast<const float4*>(Wcol + (k    ) * HID + c4);
            float4 w1 = *reinterpret_cast<const float4*>(Wcol + (k + 1) * HID + c4);
            float4 w2 = *reinterpret_cast<const float4*>(Wcol + (k + 2) * HID + c4);
            float4 w3 = *reinterpret_cast<const float4*>(Wcol + (k + 3) * HID + c4);
            acc.x += a4.x * w0.x + a4.y * w1.x + a4.z * w2.x + a4.w * w3.x;
            acc.y += a4.x * w0.y + a4.y * w1.y + a4.z * w2.y + a4.w * w3.y;
            acc.z += a4.x * w0.z + a4.y * w1.z + a4.z * w2.z + a4.w * w3.z;
            acc.w += a4.x * w0.w + a4.y * w1.w + a4.z * w2.w + a4.w * w3.w;
        }
        int row = rb + r;
        if (row < M)
            *reinterpret_cast<float4*>(&OUT[(size_t)row * HID + c4]) = acc;
        __syncthreads();
    }
}

// ---------------- segment softmax (no-max variant; 2 edge passes) ----------------
__global__ void init_seg_kernel()
{
    for (int i = blockIdx.x * blockDim.x + threadIdx.x;
         i < NNODES * HID; i += gridDim.x * blockDim.x) {
        g_agg[i] = 0.f;
        if (i < NNODES * HEADS) g_s[i] = 0.f;
    }
}

// pass A: e = exp(SCALE * dot8(xl[dst], xr[src])); alpha <- e; s[dst] += e
__global__ void edge_alpha_kernel(const int* __restrict__ src, const int* __restrict__ dst)
{
    int warp = (blockIdx.x * blockDim.x + threadIdx.x) >> 5;
    int lane = threadIdx.x & 31;
    if (warp >= EEDGES) return;
    int sp = src[warp], d = dst[warp];
    const float* xi = g_xl + (size_t)d  * HID;
    const float* xj = g_xr + (size_t)sp * HID;
    float p0 = xi[lane]      * xj[lane];
    float p1 = xi[lane + 32] * xj[lane + 32];
#pragma unroll
    for (int off = 4; off; off >>= 1) {
        p0 += __shfl_down_sync(0xffffffffu, p0, off);
        p1 += __shfl_down_sync(0xffffffffu, p1, off);
    }
    if ((lane & 7) == 0) {
        int h = lane >> 3;
        float e0 = expf(p0 * SCALE);
        float e1 = expf(p1 * SCALE);
        g_alpha[(size_t)warp * 8 + h]     = e0;
        g_alpha[(size_t)warp * 8 + 4 + h] = e1;
        atomicAdd(&g_s[(size_t)d * 8 + h],     e0);
        atomicAdd(&g_s[(size_t)d * 8 + 4 + h], e1);
    }
}

// pass B: agg[dst] += xr[src] * (e / (s[dst]+1e-16))
__global__ void edge_aggr_kernel(const int* __restrict__ src, const int* __restrict__ dst)
{
    int warp = (blockIdx.x * blockDim.x + threadIdx.x) >> 5;
    int lane = threadIdx.x & 31;
    if (warp >= EEDGES) return;
    int sp = src[warp], d = dst[warp];
    int h = lane >> 3;
    float w0 = g_alpha[(size_t)warp * 8 + h];
    float w1 = g_alpha[(size_t)warp * 8 + 4 + h];
    float s0 = g_s[(size_t)d * 8 + h];
    float s1 = g_s[(size_t)d * 8 + 4 + h];
    w0 /= (s0 + 1e-16f);
    w1 /= (s1 + 1e-16f);
    float x0 = g_xr[(size_t)sp * HID + lane];
    float x1 = g_xr[(size_t)sp * HID + lane + 32];
    atomicAdd(&g_agg[(size_t)d * HID + lane],      x0 * w0);
    atomicAdd(&g_agg[(size_t)d * HID + lane + 32], x1 * w1);
}

// ---------------- host-side launch ----------------
static inline void* symv(const void* s) {
    void* p = nullptr;
    cudaGetSymbolAddress(&p, s);
    return p;
}

extern "C" void kernel_launch(void* const* d_in, const int* in_sizes, int n_in,
                              void* d_out, int out_size)
{
    const float* x        = (const float*)d_in[0];
    const int*   eidx     = (const int*)  d_in[1];
    const int*   node_ids = (const int*)  d_in[2];
    const float* prompt   = (const float*)d_in[3];
    const float* W_lin1   = (const float*)d_in[4];
    const float* W_lin2   = (const float*)d_in[5];
    const float* w_bn1    = (const float*)d_in[6];
    const float* w_bn2    = (const float*)d_in[7];
    const float* w_bn3    = (const float*)d_in[8];
    const float* W_gnn1   = (const float*)d_in[9];
    const float* W_gnn2   = (const float*)d_in[10];
    const float* W_attl   = (const float*)d_in[11];
    const float* b_attl   = (const float*)d_in[12];
    const float* W_attr   = (const float*)d_in[13];
    const float* b_attr   = (const float*)d_in[14];
    const float* W_attl1  = (const float*)d_in[15];
    const float* b_attl1  = (const float*)d_in[16];
    const float* W_attr1  = (const float*)d_in[17];
    const float* b_attr1  = (const float*)d_in[18];
    const float* W_prompt = (const float*)d_in[19];
    const float* W_g      = (const float*)d_in[20];
    const float* W_f1     = (const float*)d_in[21];
    const float* W_f2     = (const float*)d_in[22];
    const float* W_ext    = (const float*)d_in[23];

    const int* src = eidx;
    const int* dst = eidx + EEDGES;

    float* h1  = (float*)symv(g_h1);
    float* h   = (float*)symv(g_h);
    float* xl  = (float*)symv(g_xl);
    float* xr  = (float*)symv(g_xr);
    float* agg = (float*)symv(g_agg);
    float* gx  = (float*)symv(g_gx);
    float* cat = (float*)symv(g_cat);
    float* f1  = (float*)symv(g_f1);
    float* f2  = (float*)symv(g_f2);
    __nv_bfloat16* Wh = (__nv_bfloat16*)symv(g_Wh);
    __nv_bfloat16* Wl = (__nv_bfloat16*)symv(g_Wl);
    __nv_bfloat16* Ph = (__nv_bfloat16*)symv(g_Ph);
    __nv_bfloat16* Pl = (__nv_bfloat16*)symv(g_Pl);

    const int edge_warp_blocks = (EEDGES * 32 + 255) / 256;

    // weight preprocessing (tensor-path planes)
    conv_split_kernel<<<(LLMD * 128 + 511) / 512, 512>>>(W_lin1, Wh, Wl, 128, LLMD);
    conv_split_kernel<<<(LLMD * 64 + 511) / 512, 512>>>(W_prompt, Ph, Pl, 64, LLMD);

    // ---- GATBlock ----
    gemm_bf16s_kernel<8, true>
        <<<dim3(1, (NNODES + 127) / 128), 256>>>(x, Wh, Wl, h1, NNODES, LLMD, 128);
    rowops_kernel<128, false, true, false>
        <<<1024, 256>>>(h1, W_lin2, w_bn1, nullptr, h, NNODES, HID);

    // propagate 1
    attproj_kernel<<<1024, 256>>>(h, W_attl, b_attl, W_attr, b_attr, xl, xr, NNODES);
    init_seg_kernel<<<1024, 256>>>();
    edge_alpha_kernel<<<edge_warp_blocks, 256>>>(src, dst);
    edge_aggr_kernel <<<edge_warp_blocks, 256>>>(src, dst);
    rowops_kernel<64, true, true, false>
        <<<1024, 256>>>(agg, W_gnn1, w_bn2, nullptr, h, NNODES, HID);

    // propagate 2
    attproj_kernel<<<1024, 256>>>(h, W_attl1, b_attl1, W_attr1, b_attr1, xl, xr, NNODES);
    init_seg_kernel<<<1024, 256>>>();
    edge_alpha_kernel<<<edge_warp_blocks, 256>>>(src, dst);
    edge_aggr_kernel <<<edge_warp_blocks, 256>>>(src, dst);
    rowops_kernel<64, false, true, false>
        <<<1024, 256>>>(agg, W_gnn2, w_bn3, nullptr, gx, NNODES, HID);

    // ---- FusionBlock ----
    rowops_kernel<64, false, false, true>
        <<<512, 256>>>(gx, W_g, nullptr, node_ids, cat, BATCH, 128);
    gemm_bf16s_kernel<4, false>
        <<<dim3(1, BATCH / 128), 256>>>(prompt, Ph, Pl, cat + 64, BATCH, LLMD, 128);
    gemm_kernel<64,64,16,4,4,true>
        <<<dim3(640 / 64, BATCH / 64), 256>>>(cat, W_f1, f1, BATCH, 640, 128, 640);
    gemm_kernel<32,64,16,2,4,false>
        <<<dim3(1, BATCH / 32), 256>>>(f1, W_f2, f2, BATCH, 64, 640, 64);
    gemm_kernel<64,64,16,4,4,false>
        <<<dim3(LLMD / 64, BATCH / 64), 256>>>(f2, W_ext, (float*)d_out, BATCH, LLMD, 64, LLMD);
}